// round 13
// baseline (speedup 1.0000x reference)
#include <cuda_runtime.h>
#include <cstdint>

// Problem: B=8192, K=1024, T=16384
// reference slices recomped[:, 1:2]  =>  only batch_indices[1] matters:
// out[i] = sum_k targets[i,k] * temporal_bases[batch_indices[1],k] * scaling[k]
//
// R5 weight path (smem, one L2 read per block) + R10 geometry
// (single perfectly-balanced wave: 1024 blocks, 7 CTAs/SM x 152 SMs = 1064).

static constexpr int K  = 1024;
static constexpr int K4 = K / 4;                       // 256 float4 per row
static constexpr int Tmax = 16384;
static constexpr int WARPS_PER_BLOCK = 8;
static constexpr int THREADS = WARPS_PER_BLOCK * 32;   // 256

__global__ __launch_bounds__(THREADS, 7)
void recompose_gemv_kernel(const float* __restrict__ targets,
                           const float* __restrict__ bases,
                           const float* __restrict__ scaling,
                           const int*   __restrict__ bidx32,   // raw words of batch_indices
                           float* __restrict__ out) {
    __shared__ float4 w4[K4];   // 4 KB: scaled basis row

    // --- dtype-robust index fetch (block-uniform) ---
    // int64 array of small non-negatives => hi words (odd 32-bit slots) are 0.
    int hi_or = bidx32[1] | bidx32[3] | bidx32[5] | bidx32[7];
    long long t;
    if (hi_or == 0) {
        t = (long long)bidx32[2];   // int64 layout: element 1 = words {2,3}
    } else {
        t = (long long)bidx32[1];   // int32 layout: element 1 = word 1
    }
    if (t < 0) t = 0;
    if (t >= Tmax) t = Tmax - 1;    // never fault, even if detection is wrong

    const float4* brow = reinterpret_cast<const float4*>(bases + (size_t)t * K);
    const float4* s4   = reinterpret_cast<const float4*>(scaling);
    {
        int i = threadIdx.x;        // THREADS == 256 == K4: exactly one float4 each
        float4 b = brow[i];
        float4 s = s4[i];
        w4[i] = make_float4(b.x * s.x, b.y * s.y, b.z * s.z, b.w * s.w);
    }
    __syncthreads();

    int warp = threadIdx.x >> 5;
    int lane = threadIdx.x & 31;
    int row  = blockIdx.x * WARPS_PER_BLOCK + warp;

    const float4* a4 = reinterpret_cast<const float4*>(targets + (size_t)row * K);

    float acc = 0.0f;
#pragma unroll
    for (int i = 0; i < 8; i++) {            // 8 independent streaming LDG.128
        float4 a = a4[lane + i * 32];
        float4 w = w4[lane + i * 32];
        acc += a.x * w.x + a.y * w.y + a.z * w.z + a.w * w.w;
    }

#pragma unroll
    for (int off = 16; off; off >>= 1)
        acc += __shfl_xor_sync(0xffffffffu, acc, off);

    if (lane == 0)
        out[row] = acc;
}

extern "C" void kernel_launch(void* const* d_in, const int* in_sizes, int n_in,
                              void* d_out, int out_size) {
    // Identify inputs by element count, not position.
    const float* targets = nullptr;   // 8192*1024  = 8388608
    const float* bases   = nullptr;   // 16384*1024 = 16777216
    const float* scaling = nullptr;   // 1024
    const int*   bidx    = nullptr;   // 8192 (int32 or int64 — kernel detects)

    for (int i = 0; i < n_in; i++) {
        switch (in_sizes[i]) {
            case 8388608:  targets = (const float*)d_in[i]; break;
            case 16777216: bases   = (const float*)d_in[i]; break;
            case 1024:     scaling = (const float*)d_in[i]; break;
            case 8192:     bidx    = (const int*)d_in[i];   break;
            default: break;
        }
    }

    float* out = (float*)d_out;   // [8192]

    const int B = 8192;
    const int grid = B / WARPS_PER_BLOCK;   // 1024 blocks, single balanced wave

    recompose_gemv_kernel<<<grid, THREADS>>>(targets, bases, scaling, bidx, out);
}